// round 1
// baseline (speedup 1.0000x reference)
#include <cuda_runtime.h>
#include <stdint.h>

// Problem constants
#define B_ 32
#define C_ 3
#define H_ 512
#define W_ 512
#define G_ 8          // tile grid
#define TH_ 64        // tile height (H/G)
#define TW_ 64        // tile width  (W/G)
#define BINS_ 256
#define CLIPV_ 32     // int(2.0 * 4096 / 256)
#define NPLANES_ (B_*C_)          // 96
#define NTILES_ (NPLANES_*G_*G_)  // 6144
#define PLANE_PX_ (H_*W_)         // 262144

// Device scratch (no cudaMalloc allowed)
__device__ unsigned char g_img[NPLANES_ * PLANE_PX_];       // 25 MB quantized image
__device__ unsigned char g_lut[NTILES_ * BINS_];            // 1.5 MB LUTs

// ---------------------------------------------------------------------------
// Kernel 1: per-tile histogram -> clip -> redistribute -> cdf -> LUT
// Also writes quantized u8 image so pass 2 doesn't re-read fp32.
// One block (256 threads) per tile.
// ---------------------------------------------------------------------------
__global__ __launch_bounds__(256) void hist_lut_kernel(const float* __restrict__ x) {
    const int tile  = blockIdx.x;          // 0..6143
    const int plane = tile >> 6;           // /64
    const int tid6  = tile & 63;
    const int gy    = tid6 >> 3;
    const int gx    = tid6 & 7;

    __shared__ int hist[BINS_];
    __shared__ int red[BINS_];

    const int t = threadIdx.x;
    hist[t] = 0;
    __syncthreads();

    const float*   p = x     + (size_t)plane * PLANE_PX_;
    unsigned char* q = g_img + (size_t)plane * PLANE_PX_;

    // 4096 pixels, 256 threads -> 16 each; consecutive threads cover
    // consecutive columns within a row (coalesced 256B per 64-thread group).
    #pragma unroll
    for (int i = 0; i < 16; i++) {
        int pix = t + i * 256;
        int r = pix >> 6;          // 0..63
        int c = pix & 63;
        int yy = gy * TH_ + r;
        int xx = gx * TW_ + c;
        float v = p[yy * W_ + xx];
        int iv = __float2int_rn(fminf(fmaxf(v, 0.0f), 1.0f) * 255.0f); // half-even
        q[yy * W_ + xx] = (unsigned char)iv;
        atomicAdd(&hist[iv], 1);
    }
    __syncthreads();

    // Clip + excess reduction
    int h = hist[t];
    int clipped = min(h, CLIPV_);
    red[t] = h - clipped;
    __syncthreads();
    #pragma unroll
    for (int s = 128; s > 0; s >>= 1) {
        if (t < s) red[t] += red[t + s];
        __syncthreads();
    }
    const int excess    = red[0];
    const int batch_add = excess >> 8;
    const int residual  = excess - (batch_add << 8);
    const int step      = max(BINS_ / max(residual, 1), 1);
    const int add       = ((t % step) == 0 && (t / step) < residual) ? 1 : 0;
    int hf = clipped + batch_add + add;

    // Inclusive Hillis-Steele scan over 256 bins
    __syncthreads();
    hist[t] = hf;
    __syncthreads();
    #pragma unroll
    for (int off = 1; off < 256; off <<= 1) {
        int v = (t >= off) ? hist[t - off] : 0;
        __syncthreads();
        hist[t] += v;
        __syncthreads();
    }

    float cdf = (float)hist[t];
    float lut = fminf(fmaxf(rintf(cdf * (255.0f / 4096.0f)), 0.0f), 255.0f);
    g_lut[(size_t)tile * BINS_ + t] = (unsigned char)lut;
}

// ---------------------------------------------------------------------------
// Kernel 2: bilinear interpolation of 4 tile LUTs per pixel.
// Each thread handles 4 consecutive x pixels (uchar4 in, float4 out).
// ---------------------------------------------------------------------------
__global__ __launch_bounds__(256) void interp_kernel(float* __restrict__ out) {
    const int idx = blockIdx.x * blockDim.x + threadIdx.x;  // 0 .. 96*512*128-1
    const int xq    = idx & 127;            // x / 4
    const int y     = (idx >> 7) & 511;
    const int plane = idx >> 16;            // / (512*128)
    const int x0    = xq << 2;

    // y interpolation coords (matches reference: floor before clamp)
    float fy  = (float)y * (1.0f / 64.0f) - 0.5f;
    int   ty1 = (int)floorf(fy);
    float ya  = fy - (float)ty1;
    int   ty2 = min(ty1 + 1, G_ - 1);
    ty1       = max(ty1, 0);
    const float wy1 = 1.0f - ya;
    const float wy2 = ya;

    const unsigned char* lutp = g_lut + (size_t)plane * (G_ * G_ * BINS_);
    const size_t poff = (size_t)plane * PLANE_PX_ + (size_t)y * W_ + x0;

    uchar4 pix = *reinterpret_cast<const uchar4*>(g_img + poff);
    int vs[4] = { pix.x, pix.y, pix.z, pix.w };

    float res[4];
    #pragma unroll
    for (int k = 0; k < 4; k++) {
        int xx = x0 + k;
        float fx  = (float)xx * (1.0f / 64.0f) - 0.5f;
        int   tx1 = (int)floorf(fx);
        float xa  = fx - (float)tx1;
        int   tx2 = min(tx1 + 1, G_ - 1);
        tx1       = max(tx1, 0);
        float wx1 = 1.0f - xa;
        float wx2 = xa;

        int v = vs[k];
        float g11 = (float)lutp[(ty1 * G_ + tx1) * BINS_ + v];
        float g12 = (float)lutp[(ty1 * G_ + tx2) * BINS_ + v];
        float g21 = (float)lutp[(ty2 * G_ + tx1) * BINS_ + v];
        float g22 = (float)lutp[(ty2 * G_ + tx2) * BINS_ + v];

        float r = g11 * (wy1 * wx1) + g12 * (wy1 * wx2)
                + g21 * (wy2 * wx1) + g22 * (wy2 * wx2);
        res[k] = fminf(fmaxf(rintf(r), 0.0f), 255.0f) * (1.0f / 255.0f);
    }

    *reinterpret_cast<float4*>(out + poff) = make_float4(res[0], res[1], res[2], res[3]);
}

extern "C" void kernel_launch(void* const* d_in, const int* in_sizes, int n_in,
                              void* d_out, int out_size) {
    const float* x = (const float*)d_in[0];
    float* out = (float*)d_out;

    hist_lut_kernel<<<NTILES_, 256>>>(x);

    const int total_threads = NPLANES_ * H_ * (W_ / 4);  // 6,291,456
    interp_kernel<<<total_threads / 256, 256>>>(out);
}

// round 2
// speedup vs baseline: 1.6104x; 1.6104x over previous
#include <cuda_runtime.h>
#include <stdint.h>

// Problem constants
#define B_ 32
#define C_ 3
#define H_ 512
#define W_ 512
#define G_ 8          // tile grid
#define BINS_ 256
#define CLIPV_ 32     // int(2.0 * 4096 / 256)
#define NPLANES_ (B_*C_)          // 96
#define NTILES_ (NPLANES_*G_*G_)  // 6144
#define PLANE_PX_ (H_*W_)         // 262144

// Device scratch (no cudaMalloc allowed)
__device__ unsigned char g_img[NPLANES_ * PLANE_PX_];       // 25 MB quantized image
__device__ unsigned char g_lut[NTILES_ * BINS_];            // 1.5 MB LUTs

// ---------------------------------------------------------------------------
// Kernel 1: per-tile histogram -> clip -> redistribute -> cdf -> LUT
// Also writes quantized u8 image so pass 2 doesn't re-read fp32.
// One block (256 threads) per tile; float4 loads, warp-shuffle scan.
// ---------------------------------------------------------------------------
__global__ __launch_bounds__(256) void hist_lut_kernel(const float* __restrict__ x) {
    const int tile  = blockIdx.x;          // 0..6143
    const int plane = tile >> 6;
    const int gy    = (tile >> 3) & 7;
    const int gx    = tile & 7;

    __shared__ int hist[BINS_];
    __shared__ int wsum[8];

    const int t    = threadIdx.x;
    const int lane = t & 31;
    const int warp = t >> 5;
    hist[t] = 0;
    __syncthreads();

    const float*   p = x     + (size_t)plane * PLANE_PX_;
    unsigned char* q = g_img + (size_t)plane * PLANE_PX_;

    // 4096 pixels -> 1024 float4; 256 threads x 4 iterations.
    #pragma unroll
    for (int i = 0; i < 4; i++) {
        int p4 = i * 256 + t;               // 0..1023
        int r  = p4 >> 4;                   // 0..63 (row within tile)
        int c  = (p4 & 15) << 2;            // 0..60
        size_t off = (size_t)(gy * 64 + r) * W_ + gx * 64 + c;
        float4 v = *reinterpret_cast<const float4*>(p + off);
        int i0 = __float2int_rn(fminf(fmaxf(v.x, 0.0f), 1.0f) * 255.0f);
        int i1 = __float2int_rn(fminf(fmaxf(v.y, 0.0f), 1.0f) * 255.0f);
        int i2 = __float2int_rn(fminf(fmaxf(v.z, 0.0f), 1.0f) * 255.0f);
        int i3 = __float2int_rn(fminf(fmaxf(v.w, 0.0f), 1.0f) * 255.0f);
        uchar4 pk = make_uchar4((unsigned char)i0, (unsigned char)i1,
                                (unsigned char)i2, (unsigned char)i3);
        *reinterpret_cast<uchar4*>(q + off) = pk;
        atomicAdd(&hist[i0], 1);
        atomicAdd(&hist[i1], 1);
        atomicAdd(&hist[i2], 1);
        atomicAdd(&hist[i3], 1);
    }
    __syncthreads();

    // Clip + excess reduction (warp shuffle)
    int h = hist[t];
    int clipped = min(h, CLIPV_);
    int ex = h - clipped;
    #pragma unroll
    for (int o = 16; o > 0; o >>= 1) ex += __shfl_down_sync(0xffffffffu, ex, o);
    if (lane == 0) wsum[warp] = ex;
    __syncthreads();
    if (t == 0) {
        int s = 0;
        #pragma unroll
        for (int i = 0; i < 8; i++) s += wsum[i];
        wsum[0] = s;
    }
    __syncthreads();
    const int excess    = wsum[0];
    const int batch_add = excess >> 8;
    const int residual  = excess - (batch_add << 8);
    const int step      = max(BINS_ / max(residual, 1), 1);
    const int add       = ((t % step) == 0 && (t / step) < residual) ? 1 : 0;
    int hf = clipped + batch_add + add;

    // Inclusive scan: warp shfl + cross-warp fixup
    int inc = hf;
    #pragma unroll
    for (int o = 1; o < 32; o <<= 1) {
        int n = __shfl_up_sync(0xffffffffu, inc, o);
        if (lane >= o) inc += n;
    }
    __syncthreads();   // wsum reuse
    if (lane == 31) wsum[warp] = inc;
    __syncthreads();
    if (t == 0) {
        int s = 0;
        #pragma unroll
        for (int i = 0; i < 8; i++) { int tmp = wsum[i]; wsum[i] = s; s += tmp; }
    }
    __syncthreads();
    float cdf = (float)(inc + wsum[warp]);

    float lut = fminf(fmaxf(rintf(cdf * (255.0f / 4096.0f)), 0.0f), 255.0f);
    g_lut[(size_t)tile * BINS_ + t] = (unsigned char)lut;
}

// ---------------------------------------------------------------------------
// Kernel 2: bilinear interpolation. One block per tile; 4 packed quadrant
// LUTs in shared (one u32 holds all 4 corner values for a gray level).
// Per pixel: 1 LDS.32 + PRMT byte->float + 4 FMA. Exact fp32 arithmetic.
// ---------------------------------------------------------------------------
__global__ __launch_bounds__(256) void interp_kernel(float* __restrict__ out) {
    const int tile  = blockIdx.x;
    const int plane = tile >> 6;
    const int gy    = (tile >> 3) & 7;
    const int gx    = tile & 7;

    __shared__ uint32_t qlut[4 * BINS_];

    const int t = threadIdx.x;
    const unsigned char* lutp = g_lut + (size_t)plane * (G_ * G_ * BINS_);

    const int r_top[2] = { max(gy - 1, 0), gy };            // rows for top half
    const int r_bot[2] = { gy, min(gy + 1, G_ - 1) };       // rows for bottom half
    const int c_lft[2] = { max(gx - 1, 0), gx };
    const int c_rgt[2] = { gx, min(gx + 1, G_ - 1) };

    #pragma unroll
    for (int qd = 0; qd < 4; qd++) {
        const int* rr = (qd & 2) ? r_bot : r_top;
        const int* cc = (qd & 1) ? c_rgt : c_lft;
        uint32_t b0 = lutp[(rr[0] * G_ + cc[0]) * BINS_ + t];
        uint32_t b1 = lutp[(rr[0] * G_ + cc[1]) * BINS_ + t];
        uint32_t b2 = lutp[(rr[1] * G_ + cc[0]) * BINS_ + t];
        uint32_t b3 = lutp[(rr[1] * G_ + cc[1]) * BINS_ + t];
        qlut[(qd << 8) + t] = b0 | (b1 << 8) | (b2 << 16) | (b3 << 24);
    }
    __syncthreads();

    const unsigned char* img = g_img + (size_t)plane * PLANE_PX_;
    float* op = out + (size_t)plane * PLANE_PX_;

    const int tr    = t >> 4;           // 0..15 (row slice)
    const int c4    = (t & 15) << 2;    // column within tile, 4-aligned
    const int xhalf = (c4 >= 32) ? 1 : 0;

    float wx1[4], wx2[4];
    #pragma unroll
    for (int k = 0; k < 4; k++) {
        float xa = (float)((c4 + k + 32) & 63) * (1.0f / 64.0f);
        wx2[k] = xa;
        wx1[k] = 1.0f - xa;
    }

    #pragma unroll
    for (int i = 0; i < 4; i++) {
        const int r = i * 16 + tr;                   // 0..63 row within tile
        const int y = gy * 64 + r;
        float ya  = (float)((r + 32) & 63) * (1.0f / 64.0f);
        float wy2 = ya, wy1 = 1.0f - ya;
        const uint32_t* ql = &qlut[(((r >= 32) ? 2 : 0) + xhalf) << 8];

        const size_t off = (size_t)y * W_ + gx * 64 + c4;
        uchar4 pix = *reinterpret_cast<const uchar4*>(img + off);
        int vs[4] = { pix.x, pix.y, pix.z, pix.w };

        float res[4];
        #pragma unroll
        for (int k = 0; k < 4; k++) {
            uint32_t pk = ql[vs[k]];
            float g0 = __uint_as_float(__byte_perm(pk, 0x4B000000u, 0x7650)) - 8388608.0f;
            float g1 = __uint_as_float(__byte_perm(pk, 0x4B000000u, 0x7651)) - 8388608.0f;
            float g2 = __uint_as_float(__byte_perm(pk, 0x4B000000u, 0x7652)) - 8388608.0f;
            float g3 = __uint_as_float(__byte_perm(pk, 0x4B000000u, 0x7653)) - 8388608.0f;
            float rr = g0 * (wy1 * wx1[k]) + g1 * (wy1 * wx2[k])
                     + g2 * (wy2 * wx1[k]) + g3 * (wy2 * wx2[k]);
            res[k] = fminf(fmaxf(rintf(rr), 0.0f), 255.0f) * (1.0f / 255.0f);
        }
        *reinterpret_cast<float4*>(op + off) = make_float4(res[0], res[1], res[2], res[3]);
    }
}

extern "C" void kernel_launch(void* const* d_in, const int* in_sizes, int n_in,
                              void* d_out, int out_size) {
    const float* x = (const float*)d_in[0];
    float* out = (float*)d_out;

    hist_lut_kernel<<<NTILES_, 256>>>(x);
    interp_kernel<<<NTILES_, 256>>>(out);
}